// round 11
// baseline (speedup 1.0000x reference)
#include <cuda_runtime.h>
#include <cuda_bf16.h>

#define BATCH  4
#define SEQ    2048
#define DMODEL 4096
#define ELOC   512
#define MROWS  8192
#define QSCALE 0.08838834764831845f

#define BM 128
#define BN 128
#define BK 32
#define NTH 256

typedef __nv_bfloat16 bf16;
typedef unsigned int u32;

// ---------------- SMEM map (bytes) ----------------
#define ROWB    80                 // 32 bf16 (64B) + 16B pad: conflict-free
#define OFF_AH  0
#define OFF_AL  (128*ROWB)         // 10240
#define OFF_BH  (2*128*ROWB)       // 20480
#define OFF_BL  (3*128*ROWB)       // 30720
#define STGB    (4*128*ROWB)       // 40960
#define EPS     132                // f32 words per epilogue row (mode 1 only)
#define SMEM_TOTAL (2*STGB)        // 81920  (mode-1 staging 67584 fits inside)

// ---------------- scratch (static device arrays) ----------------
__device__ bf16  g_xhi [(size_t)MROWS*DMODEL];
__device__ bf16  g_xlo [(size_t)MROWS*DMODEL];
__device__ bf16  g_Wqhi[(size_t)ELOC*DMODEL];
__device__ bf16  g_Wqlo[(size_t)ELOC*DMODEL];
__device__ bf16  g_Wkhi[(size_t)ELOC*DMODEL];
__device__ bf16  g_Wklo[(size_t)ELOC*DMODEL];
__device__ bf16  g_Wvhi[(size_t)ELOC*DMODEL];
__device__ bf16  g_Wvlo[(size_t)ELOC*DMODEL];
__device__ bf16  g_Wohi[(size_t)DMODEL*ELOC];
__device__ bf16  g_Wolo[(size_t)DMODEL*ELOC];
__device__ bf16  g_Qhi [(size_t)MROWS*ELOC];
__device__ bf16  g_Qlo [(size_t)MROWS*ELOC];
__device__ bf16  g_Khi [(size_t)MROWS*ELOC];
__device__ bf16  g_Klo [(size_t)MROWS*ELOC];
__device__ bf16  g_VThi[(size_t)BATCH*ELOC*SEQ];
__device__ bf16  g_VTlo[(size_t)BATCH*ELOC*SEQ];
__device__ float g_S   [(size_t)BATCH*SEQ*SEQ];
__device__ bf16  g_Phi [(size_t)BATCH*SEQ*SEQ];
__device__ bf16  g_Plo [(size_t)BATCH*SEQ*SEQ];
__device__ bf16  g_AThi[(size_t)BATCH*ELOC*SEQ];
__device__ bf16  g_ATlo[(size_t)BATCH*ELOC*SEQ];

// ---------------- helpers ----------------
__device__ __forceinline__ u32 smem_u32(const void* p) {
    u32 a;
    asm("{ .reg .u64 t; cvta.to.shared.u64 t, %1; cvt.u32.u64 %0, t; }"
        : "=r"(a) : "l"(p));
    return a;
}
__device__ __forceinline__ void cpa(u32 d, const void* s) {
    asm volatile("cp.async.cg.shared.global [%0], [%1], 16;" :: "r"(d), "l"(s));
}
__device__ __forceinline__ void cp_commit() {
    asm volatile("cp.async.commit_group;" ::: "memory");
}
template<int N> __device__ __forceinline__ void cp_wait() {
    asm volatile("cp.async.wait_group %0;" :: "n"(N) : "memory");
}
__device__ __forceinline__ void ldsm4(u32* r, u32 a) {
    asm volatile("ldmatrix.sync.aligned.m8n8.x4.shared.b16 {%0,%1,%2,%3}, [%4];"
                 : "=r"(r[0]), "=r"(r[1]), "=r"(r[2]), "=r"(r[3]) : "r"(a));
}
__device__ __forceinline__ void mma_bf16(float* c, const u32* a, u32 b0, u32 b1) {
    asm volatile(
        "mma.sync.aligned.m16n8k16.row.col.f32.bf16.bf16.f32 "
        "{%0,%1,%2,%3}, {%4,%5,%6,%7}, {%8,%9}, {%0,%1,%2,%3};"
        : "+f"(c[0]), "+f"(c[1]), "+f"(c[2]), "+f"(c[3])
        : "r"(a[0]), "r"(a[1]), "r"(a[2]), "r"(a[3]), "r"(b0), "r"(b1));
}
__device__ __forceinline__ u32 pk(bf16 a, bf16 b) {
    return (u32)__bfloat16_as_ushort(a) | ((u32)__bfloat16_as_ushort(b) << 16);
}
__device__ __forceinline__ u32 pk2f(float v0, float v1) {
    return pk(__float2bfloat16(v0), __float2bfloat16(v1));
}
__device__ __forceinline__ u32 pk2e(float v0, float v1) {
    bf16 h0 = __float2bfloat16(v0), h1 = __float2bfloat16(v1);
    return pk(__float2bfloat16(v0 - __bfloat162float(h0)),
              __float2bfloat16(v1 - __bfloat162float(h1)));
}

// ============================================================================
// HMMA NT GEMM (ldmatrix feeds), hi/lo bf16 split, 3 accumulating passes.
// D[m,n] = (sum_k A[m,k]*B[n,k]) * scale + bias[n]
// mode 0: split-bf16 row-major C[m,n]
// mode 1: split-bf16 TRANSPOSED C[n,m], per-batch fold by m0/2048 (V -> VT)
// mode 2: fp32 row-major Cf[m,n]
// Tiling identical to the R7 kernel that passed at 2035.9us; only the
// fragment loads changed (scalar LDS -> ldmatrix.x4) + register epilogue.
// ============================================================================
__global__ void __launch_bounds__(NTH, 1)
gemm_mma(const bf16* __restrict__ Ahi, const bf16* __restrict__ Alo,
         const bf16* __restrict__ Bhi, const bf16* __restrict__ Blo,
         int lda, int ldb, int K,
         long long aStr, long long bStr, long long cStr,
         const float* __restrict__ bias, float scale, int mode,
         bf16* __restrict__ Chi, bf16* __restrict__ Clo,
         float* __restrict__ Cf, int ldc)
{
    extern __shared__ char smem[];
    const int tid  = threadIdx.x;
    const int lane = tid & 31;
    const int wid  = tid >> 5;
    const int wm   = wid >> 1;          // 0..3
    const int wn   = wid & 1;           // 0..1
    const int g    = lane >> 2;         // 0..7
    const int t    = lane & 3;          // 0..3
    const int m0 = blockIdx.y * BM;
    const int n0 = blockIdx.x * BN;
    const int bz = blockIdx.z;

    Ahi += (long long)bz * aStr;  Alo += (long long)bz * aStr;
    Bhi += (long long)bz * bStr;  Blo += (long long)bz * bStr;
    if (Chi) { Chi += (long long)bz * cStr; Clo += (long long)bz * cStr; }
    if (Cf)    Cf += (long long)bz * cStr;

    const u32 sb = smem_u32(smem);
    const bf16* Abh = Ahi + (size_t)m0 * lda;
    const bf16* Abl = Alo + (size_t)m0 * lda;
    const bf16* Bbh = Bhi + (size_t)n0 * ldb;
    const bf16* Bbl = Blo + (size_t)n0 * ldb;

    float acc[2][8][4];
#pragma unroll
    for (int mi = 0; mi < 2; mi++)
#pragma unroll
        for (int ni = 0; ni < 8; ni++)
#pragma unroll
            for (int j = 0; j < 4; j++) acc[mi][ni][j] = 0.f;

    const int nCh = K / BK;

    auto issue = [&](int ch) {
        const u32 stg = sb + (u32)(ch & 1) * STGB;
        const size_t ko = (size_t)ch * BK;
#pragma unroll
        for (int i = 0; i < 2; i++) {                // 128 rows x 4 chunks each
            int idx = tid + i * NTH;
            int r = idx >> 2, cc = idx & 3;
            u32 d = stg + (u32)(r * ROWB + cc * 16);
            size_t ea = (size_t)r * lda + ko + cc * 8;
            size_t eb = (size_t)r * ldb + ko + cc * 8;
            cpa(d + OFF_AH, Abh + ea);
            cpa(d + OFF_AL, Abl + ea);
            cpa(d + OFF_BH, Bbh + eb);
            cpa(d + OFF_BL, Bbl + eb);
        }
    };

    auto compute = [&](int s) {
        const u32 stg = sb + (u32)s * STGB;
#pragma unroll
        for (int kh = 0; kh < 2; kh++) {
            const int kb = kh * 32;
            u32 ah[2][4], al[2][4];
#pragma unroll
            for (int mi = 0; mi < 2; mi++) {
                int row = wm * 32 + mi * 16 + (lane & 15);
                u32 a = stg + (u32)(row * ROWB) + kb + ((lane >> 4) << 4);
                ldsm4(ah[mi], a + OFF_AH);
                ldsm4(al[mi], a + OFF_AL);
            }
#pragma unroll
            for (int nip = 0; nip < 4; nip++) {
                int row = wn * 64 + nip * 16 + ((lane >> 4) << 3) + (lane & 7);
                u32 b = stg + (u32)(row * ROWB) + kb + (((lane >> 3) & 1) << 4);
                u32 bh[4], bl[4];
                ldsm4(bh, b + OFF_BH);
                ldsm4(bl, b + OFF_BL);
#pragma unroll
                for (int mi = 0; mi < 2; mi++) {
                    mma_bf16(acc[mi][2*nip],   ah[mi], bh[0], bh[1]);
                    mma_bf16(acc[mi][2*nip],   ah[mi], bl[0], bl[1]);
                    mma_bf16(acc[mi][2*nip],   al[mi], bh[0], bh[1]);
                    mma_bf16(acc[mi][2*nip+1], ah[mi], bh[2], bh[3]);
                    mma_bf16(acc[mi][2*nip+1], ah[mi], bl[2], bl[3]);
                    mma_bf16(acc[mi][2*nip+1], al[mi], bh[2], bh[3]);
                }
            }
        }
    };

    issue(0); cp_commit();
#pragma unroll 1
    for (int ch = 0; ch < nCh; ch++) {
        if (ch + 1 < nCh) { issue(ch + 1); cp_commit(); cp_wait<1>(); }
        else              { cp_wait<0>(); }
        __syncthreads();
        compute(ch & 1);
        __syncthreads();
    }

    // ---- epilogue ----
    if (mode == 1) {
        // stage f32 tile in SMEM, then transpose-store per n-column
        float* ep = (float*)smem;
#pragma unroll
        for (int mi = 0; mi < 2; mi++) {
            int r0 = wm * 32 + mi * 16 + g;
#pragma unroll
            for (int ni = 0; ni < 8; ni++) {
                int c0 = wn * 64 + ni * 8 + 2 * t;
                ep[r0 * EPS + c0]           = acc[mi][ni][0];
                ep[r0 * EPS + c0 + 1]       = acc[mi][ni][1];
                ep[(r0 + 8) * EPS + c0]     = acc[mi][ni][2];
                ep[(r0 + 8) * EPS + c0 + 1] = acc[mi][ni][3];
            }
        }
        __syncthreads();
        const size_t cb = (size_t)(m0 >> 11) * ((size_t)ELOC * SEQ);
        const int mloc = m0 & (SEQ - 1);
        const int n    = tid & 127;
        const int half = tid >> 7;                    // 0: m 0-63, 1: m 64-127
        const float bb = bias ? __ldg(bias + n0 + n) : 0.f;
        bf16* ch = Chi + cb + (size_t)(n0 + n) * ldc + mloc + half * 64;
        bf16* cl = Clo + cb + (size_t)(n0 + n) * ldc + mloc + half * 64;
#pragma unroll 1
        for (int mp = 0; mp < 8; mp++) {              // 8 m per iter
            float v[8];
#pragma unroll
            for (int j = 0; j < 8; j++)
                v[j] = ep[(half * 64 + mp * 8 + j) * EPS + n] + bb;
            uint4 h4, l4;
            h4.x = pk2f(v[0], v[1]); h4.y = pk2f(v[2], v[3]);
            h4.z = pk2f(v[4], v[5]); h4.w = pk2f(v[6], v[7]);
            l4.x = pk2e(v[0], v[1]); l4.y = pk2e(v[2], v[3]);
            l4.z = pk2e(v[4], v[5]); l4.w = pk2e(v[6], v[7]);
            *reinterpret_cast<uint4*>(ch + mp * 8) = h4;
            *reinterpret_cast<uint4*>(cl + mp * 8) = l4;
        }
    } else {
        // direct register stores
#pragma unroll
        for (int mi = 0; mi < 2; mi++) {
            int r0 = m0 + wm * 32 + mi * 16 + g;
#pragma unroll
            for (int ni = 0; ni < 8; ni++) {
                int c0 = wn * 64 + ni * 8 + 2 * t;
                float b0 = 0.f, b1 = 0.f;
                if (bias) { b0 = __ldg(bias + n0 + c0); b1 = __ldg(bias + n0 + c0 + 1); }
                float v0 = acc[mi][ni][0] * scale + b0;
                float v1 = acc[mi][ni][1] * scale + b1;
                float v2 = acc[mi][ni][2] * scale + b0;
                float v3 = acc[mi][ni][3] * scale + b1;
                if (mode == 2) {
                    *(float2*)&Cf[(size_t)r0 * ldc + n0 + c0]       = make_float2(v0, v1);
                    *(float2*)&Cf[(size_t)(r0 + 8) * ldc + n0 + c0] = make_float2(v2, v3);
                } else {
                    size_t o0 = (size_t)r0 * ldc + n0 + c0;
                    size_t o1 = (size_t)(r0 + 8) * ldc + n0 + c0;
                    *(u32*)(Chi + o0) = pk2f(v0, v1);
                    *(u32*)(Clo + o0) = pk2e(v0, v1);
                    *(u32*)(Chi + o1) = pk2f(v2, v3);
                    *(u32*)(Clo + o1) = pk2e(v2, v3);
                }
            }
        }
    }
}

// ---------------- fp32 -> hi/lo bf16 split ----------------
__global__ __launch_bounds__(256)
void split_f32(const float* __restrict__ in, bf16* __restrict__ hi,
               bf16* __restrict__ lo, int n4)
{
    int i = blockIdx.x * 256 + threadIdx.x;
    if (i >= n4) return;
    float4 v = reinterpret_cast<const float4*>(in)[i];
    uint2 hp, lp;
    hp.x = pk2f(v.x, v.y); hp.y = pk2f(v.z, v.w);
    lp.x = pk2e(v.x, v.y); lp.y = pk2e(v.z, v.w);
    reinterpret_cast<uint2*>(hi)[i] = hp;
    reinterpret_cast<uint2*>(lo)[i] = lp;
}

// ---------------- masked softmax -> split-bf16 P ----------------
__global__ __launch_bounds__(256)
void softmax_split(const float* __restrict__ S, const int* __restrict__ mask,
                   bf16* __restrict__ Phi, bf16* __restrict__ Plo)
{
    const int row = blockIdx.x;
    const int b   = row >> 11;
    const float* p = S + (size_t)row * SEQ;
    const int* mrow = mask + (size_t)b * SEQ;
    const int tid = threadIdx.x;

    float vals[8];
    float mx = -3.4e38f;
#pragma unroll
    for (int i = 0; i < 8; i++) {
        int c = tid + i * 256;
        float v = p[c];
        if (mrow[c] == 0) v = -1e9f;
        vals[i] = v;
        mx = fmaxf(mx, v);
    }
    __shared__ float red[16];
#pragma unroll
    for (int o = 16; o; o >>= 1) mx = fmaxf(mx, __shfl_xor_sync(~0u, mx, o));
    if ((tid & 31) == 0) red[tid >> 5] = mx;
    __syncthreads();
    if (tid < 32) {
        float v = (tid < 8) ? red[tid] : -3.4e38f;
#pragma unroll
        for (int o = 4; o; o >>= 1) v = fmaxf(v, __shfl_xor_sync(~0u, v, o));
        if (tid == 0) red[8] = v;
    }
    __syncthreads();
    mx = red[8];

    float sum = 0.f;
#pragma unroll
    for (int i = 0; i < 8; i++) { vals[i] = __expf(vals[i] - mx); sum += vals[i]; }
#pragma unroll
    for (int o = 16; o; o >>= 1) sum += __shfl_xor_sync(~0u, sum, o);
    if ((tid & 31) == 0) red[tid >> 5] = sum;
    __syncthreads();
    if (tid < 32) {
        float v = (tid < 8) ? red[tid] : 0.f;
#pragma unroll
        for (int o = 4; o; o >>= 1) v += __shfl_xor_sync(~0u, v, o);
        if (tid == 0) red[9] = v;
    }
    __syncthreads();
    const float inv = 1.0f / red[9];

    bf16* ph = Phi + (size_t)row * SEQ;
    bf16* pl = Plo + (size_t)row * SEQ;
#pragma unroll
    for (int i = 0; i < 8; i++) {
        int c = tid + i * 256;
        float v = vals[i] * inv;
        bf16 h = __float2bfloat16(v);
        ph[c] = h;
        pl[c] = __float2bfloat16(v - __bfloat162float(h));
    }
}

// ============================================================================
extern "C" void kernel_launch(void* const* d_in, const int* in_sizes, int n_in,
                              void* d_out, int out_size)
{
    const float* x    = (const float*)d_in[0];
    const int*   mask = (const int*)  d_in[1];
    const float* Wq   = (const float*)d_in[2];
    const float* bq   = (const float*)d_in[3];
    const float* Wk   = (const float*)d_in[4];
    const float* bk   = (const float*)d_in[5];
    const float* Wv   = (const float*)d_in[6];
    const float* bv   = (const float*)d_in[7];
    const float* Wo   = (const float*)d_in[8];
    const float* bo   = (const float*)d_in[9];
    float* out = (float*)d_out;

    cudaFuncSetAttribute(gemm_mma, cudaFuncAttributeMaxDynamicSharedMemorySize,
                         SMEM_TOTAL);

    bf16 *xhi, *xlo, *Wqh, *Wql, *Wkh, *Wkl, *Wvh, *Wvl, *Woh, *Wol;
    bf16 *Qh, *Ql, *Kh, *Kl, *VTh, *VTl, *Ph, *Pl, *ATh, *ATl;
    float *S;
    cudaGetSymbolAddress((void**)&xhi, g_xhi);  cudaGetSymbolAddress((void**)&xlo, g_xlo);
    cudaGetSymbolAddress((void**)&Wqh, g_Wqhi); cudaGetSymbolAddress((void**)&Wql, g_Wqlo);
    cudaGetSymbolAddress((void**)&Wkh, g_Wkhi); cudaGetSymbolAddress((void**)&Wkl, g_Wklo);
    cudaGetSymbolAddress((void**)&Wvh, g_Wvhi); cudaGetSymbolAddress((void**)&Wvl, g_Wvlo);
    cudaGetSymbolAddress((void**)&Woh, g_Wohi); cudaGetSymbolAddress((void**)&Wol, g_Wolo);
    cudaGetSymbolAddress((void**)&Qh,  g_Qhi);  cudaGetSymbolAddress((void**)&Ql,  g_Qlo);
    cudaGetSymbolAddress((void**)&Kh,  g_Khi);  cudaGetSymbolAddress((void**)&Kl,  g_Klo);
    cudaGetSymbolAddress((void**)&VTh, g_VThi); cudaGetSymbolAddress((void**)&VTl, g_VTlo);
    cudaGetSymbolAddress((void**)&Ph,  g_Phi);  cudaGetSymbolAddress((void**)&Pl,  g_Plo);
    cudaGetSymbolAddress((void**)&ATh, g_AThi); cudaGetSymbolAddress((void**)&ATl, g_ATlo);
    cudaGetSymbolAddress((void**)&S,   g_S);

    // 0) split fp32 inputs into hi/lo bf16
    split_f32<<<MROWS*DMODEL/4/256, 256>>>(x,  xhi, xlo, MROWS*DMODEL/4);
    split_f32<<<ELOC*DMODEL/4/256,  256>>>(Wq, Wqh, Wql, ELOC*DMODEL/4);
    split_f32<<<ELOC*DMODEL/4/256,  256>>>(Wk, Wkh, Wkl, ELOC*DMODEL/4);
    split_f32<<<ELOC*DMODEL/4/256,  256>>>(Wv, Wvh, Wvl, ELOC*DMODEL/4);
    split_f32<<<DMODEL*ELOC/4/256,  256>>>(Wo, Woh, Wol, DMODEL*ELOC/4);

    dim3 blk(NTH);

    // 1) Q/K projections -> split-bf16 row-major [8192,512]
    dim3 g1(ELOC / BN, MROWS / BM, 1);
    gemm_mma<<<g1, blk, SMEM_TOTAL>>>(xhi, xlo, Wqh, Wql, DMODEL, DMODEL, DMODEL,
                                      0, 0, 0, bq, 1.0f, 0, Qh, Ql, nullptr, ELOC);
    gemm_mma<<<g1, blk, SMEM_TOTAL>>>(xhi, xlo, Wkh, Wkl, DMODEL, DMODEL, DMODEL,
                                      0, 0, 0, bk, 1.0f, 0, Kh, Kl, nullptr, ELOC);
    // 2) V projection -> TRANSPOSED split-bf16 VT[b][e][s]
    gemm_mma<<<g1, blk, SMEM_TOTAL>>>(xhi, xlo, Wvh, Wvl, DMODEL, DMODEL, DMODEL,
                                      0, 0, 0, bv, 1.0f, 1, VTh, VTl, nullptr, SEQ);

    // 3) scores = Q·K^T / sqrt(128) -> fp32 S, per batch
    dim3 g2(SEQ / BN, SEQ / BM, BATCH);
    gemm_mma<<<g2, blk, SMEM_TOTAL>>>(Qh, Ql, Kh, Kl, ELOC, ELOC, ELOC,
                                      (long long)SEQ*ELOC, (long long)SEQ*ELOC,
                                      (long long)SEQ*SEQ,
                                      nullptr, QSCALE, 2, nullptr, nullptr, S, SEQ);

    // 4) masked softmax -> split-bf16 P
    softmax_split<<<MROWS, 256>>>(S, mask, Ph, Pl);

    // 5) AT[b][e][q] = sum_s VT[b][e][s]*P[b][q][s] -> split-bf16 [e][q]
    dim3 g3(SEQ / BN, ELOC / BM, BATCH);
    gemm_mma<<<g3, blk, SMEM_TOTAL>>>(VTh, VTl, Ph, Pl, SEQ, SEQ, SEQ,
                                      (long long)ELOC*SEQ, (long long)SEQ*SEQ,
                                      (long long)ELOC*SEQ,
                                      nullptr, 1.0f, 0, ATh, ATl, nullptr, SEQ);

    // 6) out = attn_view·Wo^T + bo ; AT[b] flat == attn_view[b] flat [2048,512]
    dim3 g4(DMODEL / BN, MROWS / BM, 1);
    gemm_mma<<<g4, blk, SMEM_TOTAL>>>(ATh, ATl, Woh, Wol, ELOC, ELOC, ELOC,
                                      0, 0, 0, bo, 1.0f, 2, nullptr, nullptr,
                                      out, DMODEL);
}

// round 14
// speedup vs baseline: 1.8254x; 1.8254x over previous
#include <cuda_runtime.h>

#define BATCH  4
#define SEQ    2048
#define DMODEL 4096
#define ELOC   512
#define MROWS  8192
#define QSCALE 0.08838834764831845f

#define BM  128
#define BN  128
#define BKI 64              // s8 elems (=bytes) of K per chunk
#define NTH 256

typedef signed char s8;
typedef unsigned int u32;

// ---------------- SMEM map ----------------
#define ROWB   80           // 64 B k-extent + 16 B pad
#define OFF_A1 0
#define OFF_A0 (128*ROWB)   // 10240
#define OFF_B1 (2*128*ROWB)
#define OFF_B0 (3*128*ROWB)
#define STGB   (4*128*ROWB) // 40960
#define EPS    132          // f32 words per staging row (mode 3)
#define SMEM_TOTAL (2*STGB) // 81920 (mode-3 staging 67584 fits)
#define FOLD   ((size_t)ELOC*SEQ)

// ---------------- scratch ----------------
__device__ s8    g_x1 [(size_t)MROWS*DMODEL];
__device__ s8    g_x0 [(size_t)MROWS*DMODEL];
__device__ float g_rsx[MROWS];
__device__ s8    g_wq1[(size_t)ELOC*DMODEL];
__device__ s8    g_wq0[(size_t)ELOC*DMODEL];
__device__ float g_rswq[ELOC];
__device__ s8    g_wk1[(size_t)ELOC*DMODEL];
__device__ s8    g_wk0[(size_t)ELOC*DMODEL];
__device__ float g_rswk[ELOC];
__device__ s8    g_wv1[(size_t)ELOC*DMODEL];
__device__ s8    g_wv0[(size_t)ELOC*DMODEL];
__device__ float g_rswv[ELOC];
__device__ s8    g_wo1[(size_t)DMODEL*ELOC];
__device__ s8    g_wo0[(size_t)DMODEL*ELOC];
__device__ float g_rswo[DMODEL];
__device__ float g_Qf [(size_t)MROWS*ELOC];
__device__ float g_Kf [(size_t)MROWS*ELOC];
__device__ float g_VTf[(size_t)BATCH*ELOC*SEQ];
__device__ float g_ATf[(size_t)MROWS*ELOC];   // = [BATCH][ELOC][SEQ] e-major flat
__device__ float g_Sf [(size_t)BATCH*SEQ*SEQ];
__device__ s8    g_q1 [(size_t)MROWS*ELOC];
__device__ s8    g_q0 [(size_t)MROWS*ELOC];
__device__ float g_rsq[MROWS];
__device__ s8    g_k1 [(size_t)MROWS*ELOC];
__device__ s8    g_k0 [(size_t)MROWS*ELOC];
__device__ float g_rsk[MROWS];
__device__ s8    g_vt1[(size_t)BATCH*ELOC*SEQ];
__device__ s8    g_vt0[(size_t)BATCH*ELOC*SEQ];
__device__ float g_rsvt[BATCH*ELOC];
__device__ s8    g_p1 [(size_t)BATCH*SEQ*SEQ];
__device__ s8    g_p0 [(size_t)BATCH*SEQ*SEQ];
__device__ float g_rsp[MROWS];
__device__ s8    g_at1[(size_t)MROWS*ELOC];
__device__ s8    g_at0[(size_t)MROWS*ELOC];
__device__ float g_rsat[MROWS];

// ---------------- helpers ----------------
__device__ __forceinline__ u32 smem_u32(const void* p) {
    u32 a;
    asm("{ .reg .u64 t; cvta.to.shared.u64 t, %1; cvt.u32.u64 %0, t; }"
        : "=r"(a) : "l"(p));
    return a;
}
__device__ __forceinline__ void cpa(u32 d, const void* s) {
    asm volatile("cp.async.cg.shared.global [%0], [%1], 16;" :: "r"(d), "l"(s));
}
__device__ __forceinline__ void cp_commit() {
    asm volatile("cp.async.commit_group;" ::: "memory");
}
template<int N> __device__ __forceinline__ void cp_wait() {
    asm volatile("cp.async.wait_group %0;" :: "n"(N) : "memory");
}
__device__ __forceinline__ void mma_s8(int* c, const u32* a, u32 b0, u32 b1) {
    asm volatile(
        "mma.sync.aligned.m16n8k32.row.col.s32.s8.s8.s32 "
        "{%0,%1,%2,%3}, {%4,%5,%6,%7}, {%8,%9}, {%0,%1,%2,%3};"
        : "+r"(c[0]), "+r"(c[1]), "+r"(c[2]), "+r"(c[3])
        : "r"(a[0]), "r"(a[1]), "r"(a[2]), "r"(a[3]), "r"(b0), "r"(b1));
}

// ============================================================================
// s8 split NT GEMM: D[m,n] = (sum_k A[m,k]*B[n,k])*rsA[m]*rsB[n]*scale + bias[n]
//   A = A1*128 + A0 (s8 slices), same for B; 3 IMMA passes, drop A0*B0.
// mode 2: fp32 row-major Cf[m,n]
// mode 3: fp32 TRANSPOSED Cf[n, m] with batch fold cb = bz*cStr + (m0>>11)*FOLD
// ============================================================================
__global__ void __launch_bounds__(NTH, 1)
gemm_i8(const s8* __restrict__ A1, const s8* __restrict__ A0,
        const s8* __restrict__ B1, const s8* __restrict__ B0,
        const float* __restrict__ rsA, const float* __restrict__ rsB,
        int rsAs, int rsBs,
        int lda, int ldb, int K,
        long long aStr, long long bStr, long long cStr,
        const float* __restrict__ bias, float scale, int mode,
        float* __restrict__ Cf, int ldc)
{
    extern __shared__ char smem[];
    const int tid  = threadIdx.x;
    const int lane = tid & 31;
    const int wid  = tid >> 5;
    const int wm   = wid >> 1;          // 0..3
    const int wn   = wid & 1;           // 0..1
    const int g    = lane >> 2;         // 0..7
    const int t    = lane & 3;          // 0..3
    const int m0 = blockIdx.y * BM;
    const int n0 = blockIdx.x * BN;
    const int bz = blockIdx.z;

    const s8* Aa1 = A1 + (long long)bz * aStr + (size_t)m0 * lda;
    const s8* Aa0 = A0 + (long long)bz * aStr + (size_t)m0 * lda;
    const s8* Bb1 = B1 + (long long)bz * bStr + (size_t)n0 * ldb;
    const s8* Bb0 = B0 + (long long)bz * bStr + (size_t)n0 * ldb;
    const float* rsAp = rsA + (size_t)bz * rsAs + m0;
    const float* rsBp = rsB + (size_t)bz * rsBs + n0;

    const u32 sb = smem_u32(smem);

    int acc1[2][8][4], accM[2][8][4];
#pragma unroll
    for (int mi = 0; mi < 2; mi++)
#pragma unroll
        for (int ni = 0; ni < 8; ni++)
#pragma unroll
            for (int j = 0; j < 4; j++) { acc1[mi][ni][j] = 0; accM[mi][ni][j] = 0; }

    const int nCh = K / BKI;

    auto issue = [&](int ch) {
        const u32 stg = sb + (u32)(ch & 1) * STGB;
        const size_t ko = (size_t)ch * BKI;
#pragma unroll
        for (int i = 0; i < 2; i++) {               // 128 rows x 4 16B chunks
            int idx = tid + i * NTH;
            int r = idx >> 2, cc = idx & 3;
            u32 d = stg + (u32)(r * ROWB + cc * 16);
            size_t ea = (size_t)r * lda + ko + cc * 16;
            size_t eb = (size_t)r * ldb + ko + cc * 16;
            cpa(d + OFF_A1, Aa1 + ea);
            cpa(d + OFF_A0, Aa0 + ea);
            cpa(d + OFF_B1, Bb1 + eb);
            cpa(d + OFF_B0, Bb0 + eb);
        }
    };

    auto compute = [&](int s) {
        const char* stg = smem + s * STGB;
#pragma unroll
        for (int kk = 0; kk < 2; kk++) {            // two k32 steps per chunk
            const int kb = kk * 32;
            u32 a1f[2][4], a0f[2][4];
#pragma unroll
            for (int mi = 0; mi < 2; mi++) {
                const char* pa = stg + (wm * 32 + mi * 16 + g) * ROWB + kb + 4 * t;
                a1f[mi][0] = *(const u32*)(pa + OFF_A1);
                a1f[mi][1] = *(const u32*)(pa + OFF_A1 + 8 * ROWB);
                a1f[mi][2] = *(const u32*)(pa + OFF_A1 + 16);
                a1f[mi][3] = *(const u32*)(pa + OFF_A1 + 8 * ROWB + 16);
                a0f[mi][0] = *(const u32*)(pa + OFF_A0);
                a0f[mi][1] = *(const u32*)(pa + OFF_A0 + 8 * ROWB);
                a0f[mi][2] = *(const u32*)(pa + OFF_A0 + 16);
                a0f[mi][3] = *(const u32*)(pa + OFF_A0 + 8 * ROWB + 16);
            }
#pragma unroll
            for (int ni = 0; ni < 8; ni++) {
                const char* pb = stg + (wn * 64 + ni * 8 + g) * ROWB + kb + 4 * t;
                u32 b1_0 = *(const u32*)(pb + OFF_B1);
                u32 b1_1 = *(const u32*)(pb + OFF_B1 + 16);
                u32 b0_0 = *(const u32*)(pb + OFF_B0);
                u32 b0_1 = *(const u32*)(pb + OFF_B0 + 16);
#pragma unroll
                for (int mi = 0; mi < 2; mi++)
                    mma_s8(acc1[mi][ni], a1f[mi], b1_0, b1_1);  // hi*hi
#pragma unroll
                for (int mi = 0; mi < 2; mi++)
                    mma_s8(accM[mi][ni], a1f[mi], b0_0, b0_1);  // hi*lo
#pragma unroll
                for (int mi = 0; mi < 2; mi++)
                    mma_s8(accM[mi][ni], a0f[mi], b1_0, b1_1);  // lo*hi
            }
        }
    };

    issue(0); cp_commit();
#pragma unroll 1
    for (int ch = 0; ch < nCh; ch++) {
        if (ch + 1 < nCh) { issue(ch + 1); cp_commit(); cp_wait<1>(); }
        else              { cp_wait<0>(); }
        __syncthreads();
        compute(ch & 1);
        __syncthreads();
    }

    // ---- epilogue ----
    if (mode == 2) {
#pragma unroll
        for (int mi = 0; mi < 2; mi++) {
            int rl = wm * 32 + mi * 16 + g;
            float ra0 = __ldg(rsAp + rl) * scale;
            float ra1 = __ldg(rsAp + rl + 8) * scale;
            int r0 = m0 + rl;
#pragma unroll
            for (int ni = 0; ni < 8; ni++) {
                int c0 = wn * 64 + ni * 8 + 2 * t;
                float rb0 = __ldg(rsBp + c0), rb1 = __ldg(rsBp + c0 + 1);
                float bb0 = bias ? __ldg(bias + n0 + c0)     : 0.f;
                float bb1 = bias ? __ldg(bias + n0 + c0 + 1) : 0.f;
                float v00 = fmaf(16384.f, (float)acc1[mi][ni][0],
                                 128.f * (float)accM[mi][ni][0]) * ra0 * rb0 + bb0;
                float v01 = fmaf(16384.f, (float)acc1[mi][ni][1],
                                 128.f * (float)accM[mi][ni][1]) * ra0 * rb1 + bb1;
                float v10 = fmaf(16384.f, (float)acc1[mi][ni][2],
                                 128.f * (float)accM[mi][ni][2]) * ra1 * rb0 + bb0;
                float v11 = fmaf(16384.f, (float)acc1[mi][ni][3],
                                 128.f * (float)accM[mi][ni][3]) * ra1 * rb1 + bb1;
                *(float2*)&Cf[(long long)bz * cStr + (size_t)r0 * ldc + n0 + c0] =
                    make_float2(v00, v01);
                *(float2*)&Cf[(long long)bz * cStr + (size_t)(r0 + 8) * ldc + n0 + c0] =
                    make_float2(v10, v11);
            }
        }
    } else {
        // mode 3: stage scaled values, transpose-store with bias
        float* ep = (float*)smem;
#pragma unroll
        for (int mi = 0; mi < 2; mi++) {
            int rl = wm * 32 + mi * 16 + g;
            float ra0 = __ldg(rsAp + rl) * scale;
            float ra1 = __ldg(rsAp + rl + 8) * scale;
#pragma unroll
            for (int ni = 0; ni < 8; ni++) {
                int c0 = wn * 64 + ni * 8 + 2 * t;
                float rb0 = __ldg(rsBp + c0), rb1 = __ldg(rsBp + c0 + 1);
                ep[rl * EPS + c0] = fmaf(16384.f, (float)acc1[mi][ni][0],
                                         128.f * (float)accM[mi][ni][0]) * ra0 * rb0;
                ep[rl * EPS + c0 + 1] = fmaf(16384.f, (float)acc1[mi][ni][1],
                                             128.f * (float)accM[mi][ni][1]) * ra0 * rb1;
                ep[(rl + 8) * EPS + c0] = fmaf(16384.f, (float)acc1[mi][ni][2],
                                               128.f * (float)accM[mi][ni][2]) * ra1 * rb0;
                ep[(rl + 8) * EPS + c0 + 1] = fmaf(16384.f, (float)acc1[mi][ni][3],
                                                   128.f * (float)accM[mi][ni][3]) * ra1 * rb1;
            }
        }
        __syncthreads();
        const size_t cb = (size_t)bz * cStr + (size_t)(m0 >> 11) * FOLD;
        const int mloc = m0 & (SEQ - 1);
        const int n    = tid & 127;
        const int half = tid >> 7;
        const float bb = bias ? __ldg(bias + n0 + n) : 0.f;
        float* Cp = Cf + cb + (size_t)(n0 + n) * ldc + mloc + half * 64;
#pragma unroll 1
        for (int mp = 0; mp < 8; mp++) {
            float v[8];
#pragma unroll
            for (int j = 0; j < 8; j++)
                v[j] = ep[(half * 64 + mp * 8 + j) * EPS + n] + bb;
            *(float4*)(Cp + mp * 8)     = make_float4(v[0], v[1], v[2], v[3]);
            *(float4*)(Cp + mp * 8 + 4) = make_float4(v[4], v[5], v[6], v[7]);
        }
    }
}

// ---------------- row-wise fp32 -> s15 (two s8 slices) quantization ----------
__global__ __launch_bounds__(256)
void quant8(const float* __restrict__ in, s8* __restrict__ q1,
            s8* __restrict__ q0, float* __restrict__ rs, int K)
{
    const int row = blockIdx.x, tid = threadIdx.x;
    const float* p = in + (size_t)row * K;
    float amax = 0.f;
    for (int c = tid; c < K; c += 256) amax = fmaxf(amax, fabsf(p[c]));
    __shared__ float red[9];
#pragma unroll
    for (int o = 16; o; o >>= 1) amax = fmaxf(amax, __shfl_xor_sync(~0u, amax, o));
    if ((tid & 31) == 0) red[tid >> 5] = amax;
    __syncthreads();
    if (tid < 32) {
        float v = (tid < 8) ? red[tid] : 0.f;
#pragma unroll
        for (int o = 4; o; o >>= 1) v = fmaxf(v, __shfl_xor_sync(~0u, v, o));
        if (tid == 0) red[8] = v;
    }
    __syncthreads();
    amax = red[8];
    const float S = amax > 0.f ? 16000.f / amax : 0.f;
    if (tid == 0) rs[row] = amax * (1.f / 16000.f);
    for (int c = tid; c < K; c += 256) {
        int q = __float2int_rn(p[c] * S);
        int hi = (q + 64) >> 7;
        q1[(size_t)row * K + c] = (s8)hi;
        q0[(size_t)row * K + c] = (s8)(q - (hi << 7));
    }
}

// ---------------- masked softmax -> quantized P + row scale ----------------
__global__ __launch_bounds__(256)
void softmax_quant(const float* __restrict__ S, const int* __restrict__ mask,
                   s8* __restrict__ p1, s8* __restrict__ p0,
                   float* __restrict__ rsP)
{
    const int row = blockIdx.x;
    const int b   = row >> 11;
    const float* p = S + (size_t)row * SEQ;
    const int* mrow = mask + (size_t)b * SEQ;
    const int tid = threadIdx.x;

    float vals[8];
    float mx = -3.4e38f;
#pragma unroll
    for (int i = 0; i < 8; i++) {
        int c = tid + i * 256;
        float v = p[c];
        if (mrow[c] == 0) v = -1e9f;
        vals[i] = v;
        mx = fmaxf(mx, v);
    }
    __shared__ float red[16];
#pragma unroll
    for (int o = 16; o; o >>= 1) mx = fmaxf(mx, __shfl_xor_sync(~0u, mx, o));
    if ((tid & 31) == 0) red[tid >> 5] = mx;
    __syncthreads();
    if (tid < 32) {
        float v = (tid < 8) ? red[tid] : -3.4e38f;
#pragma unroll
        for (int o = 4; o; o >>= 1) v = fmaxf(v, __shfl_xor_sync(~0u, v, o));
        if (tid == 0) red[8] = v;
    }
    __syncthreads();
    mx = red[8];

    float sum = 0.f;
#pragma unroll
    for (int i = 0; i < 8; i++) { vals[i] = __expf(vals[i] - mx); sum += vals[i]; }
#pragma unroll
    for (int o = 16; o; o >>= 1) sum += __shfl_xor_sync(~0u, sum, o);
    if ((tid & 31) == 0) red[tid >> 5] = sum;
    __syncthreads();
    if (tid < 32) {
        float v = (tid < 8) ? red[tid] : 0.f;
#pragma unroll
        for (int o = 4; o; o >>= 1) v += __shfl_xor_sync(~0u, v, o);
        if (tid == 0) red[9] = v;
    }
    __syncthreads();
    const float inv = 1.0f / red[9];
    // p_i = vals_i * inv; row absmax of vals = 1 -> q = rn(16000*vals_i)
    if (tid == 0) rsP[row] = inv * (1.f / 16000.f);
    s8* o1 = p1 + (size_t)row * SEQ;
    s8* o0 = p0 + (size_t)row * SEQ;
#pragma unroll
    for (int i = 0; i < 8; i++) {
        int c = tid + i * 256;
        int q = __float2int_rn(vals[i] * 16000.f);
        int hi = (q + 64) >> 7;
        o1[c] = (s8)hi;
        o0[c] = (s8)(q - (hi << 7));
    }
}

// ============================================================================
extern "C" void kernel_launch(void* const* d_in, const int* in_sizes, int n_in,
                              void* d_out, int out_size)
{
    const float* x    = (const float*)d_in[0];
    const int*   mask = (const int*)  d_in[1];
    const float* Wq   = (const float*)d_in[2];
    const float* bq   = (const float*)d_in[3];
    const float* Wk   = (const float*)d_in[4];
    const float* bk   = (const float*)d_in[5];
    const float* Wv   = (const float*)d_in[6];
    const float* bv   = (const float*)d_in[7];
    const float* Wo   = (const float*)d_in[8];
    const float* bo   = (const float*)d_in[9];
    float* out = (float*)d_out;

    cudaFuncSetAttribute(gemm_i8, cudaFuncAttributeMaxDynamicSharedMemorySize,
                         SMEM_TOTAL);

    s8 *x1, *x0, *wq1, *wq0, *wk1, *wk0, *wv1, *wv0, *wo1, *wo0;
    s8 *q1, *q0, *k1, *k0, *vt1, *vt0, *p1, *p0, *at1, *at0;
    float *rsx, *rswq, *rswk, *rswv, *rswo, *rsq, *rsk, *rsvt, *rsp, *rsat;
    float *Qf, *Kf, *VTf, *ATf, *Sf;
    cudaGetSymbolAddress((void**)&x1,  g_x1);   cudaGetSymbolAddress((void**)&x0,  g_x0);
    cudaGetSymbolAddress((void**)&rsx, g_rsx);
    cudaGetSymbolAddress((void**)&wq1, g_wq1);  cudaGetSymbolAddress((void**)&wq0, g_wq0);
    cudaGetSymbolAddress((void**)&rswq, g_rswq);
    cudaGetSymbolAddress((void**)&wk1, g_wk1);  cudaGetSymbolAddress((void**)&wk0, g_wk0);
    cudaGetSymbolAddress((void**)&rswk, g_rswk);
    cudaGetSymbolAddress((void**)&wv1, g_wv1);  cudaGetSymbolAddress((void**)&wv0, g_wv0);
    cudaGetSymbolAddress((void**)&rswv, g_rswv);
    cudaGetSymbolAddress((void**)&wo1, g_wo1);  cudaGetSymbolAddress((void**)&wo0, g_wo0);
    cudaGetSymbolAddress((void**)&rswo, g_rswo);
    cudaGetSymbolAddress((void**)&q1,  g_q1);   cudaGetSymbolAddress((void**)&q0,  g_q0);
    cudaGetSymbolAddress((void**)&rsq, g_rsq);
    cudaGetSymbolAddress((void**)&k1,  g_k1);   cudaGetSymbolAddress((void**)&k0,  g_k0);
    cudaGetSymbolAddress((void**)&rsk, g_rsk);
    cudaGetSymbolAddress((void**)&vt1, g_vt1);  cudaGetSymbolAddress((void**)&vt0, g_vt0);
    cudaGetSymbolAddress((void**)&rsvt, g_rsvt);
    cudaGetSymbolAddress((void**)&p1,  g_p1);   cudaGetSymbolAddress((void**)&p0,  g_p0);
    cudaGetSymbolAddress((void**)&rsp, g_rsp);
    cudaGetSymbolAddress((void**)&at1, g_at1);  cudaGetSymbolAddress((void**)&at0, g_at0);
    cudaGetSymbolAddress((void**)&rsat, g_rsat);
    cudaGetSymbolAddress((void**)&Qf,  g_Qf);   cudaGetSymbolAddress((void**)&Kf,  g_Kf);
    cudaGetSymbolAddress((void**)&VTf, g_VTf);  cudaGetSymbolAddress((void**)&ATf, g_ATf);
    cudaGetSymbolAddress((void**)&Sf,  g_Sf);

    // 0) quantize inputs (row-wise over the k-dim of each GEMM)
    quant8<<<MROWS,  256>>>(x,  x1,  x0,  rsx,  DMODEL);
    quant8<<<ELOC,   256>>>(Wq, wq1, wq0, rswq, DMODEL);
    quant8<<<ELOC,   256>>>(Wk, wk1, wk0, rswk, DMODEL);
    quant8<<<ELOC,   256>>>(Wv, wv1, wv0, rswv, DMODEL);
    quant8<<<DMODEL, 256>>>(Wo, wo1, wo0, rswo, ELOC);

    dim3 blk(NTH);

    // 1) Q/K projections -> fp32 [8192,512]
    dim3 g1(ELOC / BN, MROWS / BM, 1);
    gemm_i8<<<g1, blk, SMEM_TOTAL>>>(x1, x0, wq1, wq0, rsx, rswq, 0, 0,
                                     DMODEL, DMODEL, DMODEL, 0, 0, 0,
                                     bq, 1.f, 2, Qf, ELOC);
    gemm_i8<<<g1, blk, SMEM_TOTAL>>>(x1, x0, wk1, wk0, rsx, rswk, 0, 0,
                                     DMODEL, DMODEL, DMODEL, 0, 0, 0,
                                     bk, 1.f, 2, Kf, ELOC);
    // 2) V projection -> fp32 TRANSPOSED VTf[b][e][s] (batch fold on m0)
    gemm_i8<<<g1, blk, SMEM_TOTAL>>>(x1, x0, wv1, wv0, rsx, rswv, 0, 0,
                                     DMODEL, DMODEL, DMODEL, 0, 0, 0,
                                     bv, 1.f, 3, VTf, SEQ);

    // 3) re-quantize intermediates
    quant8<<<MROWS,      256>>>(Qf,  q1,  q0,  rsq,  ELOC);
    quant8<<<MROWS,      256>>>(Kf,  k1,  k0,  rsk,  ELOC);
    quant8<<<BATCH*ELOC, 256>>>(VTf, vt1, vt0, rsvt, SEQ);

    // 4) scores = Q.K^T / sqrt(128) -> fp32 Sf, per batch
    dim3 g2(SEQ / BN, SEQ / BM, BATCH);
    gemm_i8<<<g2, blk, SMEM_TOTAL>>>(q1, q0, k1, k0, rsq, rsk, SEQ, SEQ,
                                     ELOC, ELOC, ELOC,
                                     (long long)SEQ*ELOC, (long long)SEQ*ELOC,
                                     (long long)SEQ*SEQ,
                                     nullptr, QSCALE, 2, Sf, SEQ);

    // 5) masked softmax -> quantized P (scale adapts to row max)
    softmax_quant<<<MROWS, 256>>>(Sf, mask, p1, p0, rsp);

    // 6) AT[b][e][q] = sum_s VT[b][e,s]*P[b][q,s] -> fp32 ROW-MAJOR e-major.
    //    Flat per batch, AT = attnT; its [8192,512] reinterpretation IS the
    //    reference's swapaxes(1,2).reshape view (R7-validated layout).
    dim3 g3(SEQ / BN, ELOC / BM, BATCH);
    gemm_i8<<<g3, blk, SMEM_TOTAL>>>(vt1, vt0, p1, p0, rsvt, rsp, ELOC, SEQ,
                                     SEQ, SEQ, SEQ,
                                     (long long)ELOC*SEQ, (long long)SEQ*SEQ,
                                     (long long)ELOC*SEQ,
                                     nullptr, 1.f, 2, ATf, SEQ);

    // 7) re-quantize attention output as attn_view rows [8192,512]
    quant8<<<MROWS, 256>>>(ATf, at1, at0, rsat, ELOC);

    // 8) out = attn_view.Wo^T + bo -> fp32 [8192,4096]
    dim3 g4(DMODEL / BN, MROWS / BM, 1);
    gemm_i8<<<g4, blk, SMEM_TOTAL>>>(at1, at0, wo1, wo0, rsat, rswo, 0, 0,
                                     ELOC, ELOC, ELOC, 0, 0, 0,
                                     bo, 1.f, 2, out, DMODEL);
}